// round 13
// baseline (speedup 1.0000x reference)
#include <cuda_runtime.h>

#define BB 256
#define TT 256
#define CC 512
#define LL 64
#define SS 129              // 2L+1 extended states
#define NSYM 65             // [blank, l0..l63]
#define RW 68               // ring row width in floats
#define RING 32             // ring depth (rows)
#define LOG2E 1.4426950408889634f
#define LN2   0.6931471805599453f
#define EZ_EMPTY (-100000)

__device__ float g_nll[BB];
__device__ int   g_done;    // zero-init; reset by winner each launch

__device__ __forceinline__ float exp2i_pm(int d) {
    d = max(d, -127); d = min(d, 127);
    return __uint_as_float((unsigned)(127 + d) << 23);
}
__device__ __forceinline__ int ld_acq(const int* p) {
    int v;
    asm volatile("ld.acquire.cta.shared.b32 %0, [%1];"
                 : "=r"(v) : "r"((unsigned)__cvta_generic_to_shared(p)) : "memory");
    return v;
}
__device__ __forceinline__ void st_rel(int* p, int v) {
    asm volatile("st.release.cta.shared.b32 [%0], %1;"
                 :: "r"((unsigned)__cvta_generic_to_shared(p)), "r"(v) : "memory");
}

// ---------------------------------------------------------------------------
// Fused kernel: 1 block = 2 batch elements (grid 128 x 512 thr).
// Warps 0-13: producers, software-pipelined 2 rows deep (rows t, t+7 resident,
// t+14 loads issued before computing t) -> ~4KB DRAM bytes in flight per warp.
// Ring rows hold UNNORMALIZED e^x gathers; lse2[t] accumulates off-path.
// Warps 14/15: consumers (CTC recursion, per-lane pow2 scaling), apply the
// LN2*sum(lse2) correction at the end after producer done-flags.
// ---------------------------------------------------------------------------
__global__ void __launch_bounds__(512) k_fused(const float* __restrict__ logits,
                                               const int*   __restrict__ labels,
                                               const int*   __restrict__ lab_len,
                                               const int*   __restrict__ log_len,
                                               float* __restrict__ out) {
    __shared__ __align__(16) float ring[2][RING][RW];
    __shared__ float lse_s[2][TT];
    __shared__ int labels_s[2][LL];
    __shared__ int ready[2][RING];   // row t written -> value t+1
    __shared__ int consT[2];         // consumer progress
    __shared__ int pdone[2][7];      // per-producer-warp done flags

    int tid  = threadIdx.x;
    int warp = tid >> 5;
    int lane = tid & 31;

    if (tid < 2 * LL) {
        int side = tid / LL;
        labels_s[side][tid % LL] = labels[(blockIdx.x * 2 + side) * LL + (tid % LL)];
    }
    if (tid < 2 * RING) ready[tid >> 5][tid & 31] = 0;
    if (tid >= 128 && tid < 130) consT[tid - 128] = -1;
    if (tid >= 130 && tid < 144) pdone[(tid - 130) / 7][(tid - 130) % 7] = 0;
    __syncthreads();

    if (warp < 14) {
        // =================== PRODUCER ===================
        int side = warp / 7;
        int pw   = warp % 7;
        int b    = blockIdx.x * 2 + side;
        const int* lb = labels_s[side];
        const float* bbase = logits + (size_t)b * TT * CC;

        int t = pw;
        const float* rp = bbase + (size_t)t * CC;
        // rows t and t+7 resident
        const float4* r4 = reinterpret_cast<const float4*>(rp);
        float4 c0 = r4[lane], c1 = r4[lane + 32], c2 = r4[lane + 64], c3 = r4[lane + 96];
        {
            int t1 = t + 7;
            const float4* r41 = reinterpret_cast<const float4*>(
                bbase + (size_t)(t1 < TT ? t1 : 0) * CC);
            float4 d0 = r41[lane], d1 = r41[lane + 32],
                   d2 = r41[lane + 64], d3 = r41[lane + 96];

            while (t < TT) {
                // issue loads for row t+14 FIRST (keeps 2 rows of DRAM in flight)
                int t2 = t + 14;
                const float4* r42 = reinterpret_cast<const float4*>(
                    bbase + (size_t)(t2 < TT ? t2 : 0) * CC);
                float4 e0 = r42[lane], e1 = r42[lane + 32],
                       e2 = r42[lane + 64], e3 = r42[lane + 96];

                // ---- ring write for row t: raw e^x gather (L1 hits) ----
                if (t >= RING) {
                    while (ld_acq(&consT[side]) < t - (RING - 1)) __nanosleep(50);
                }
                int slot = t & (RING - 1);
                float* rrow = &ring[side][slot][0];
                #pragma unroll
                for (int j = lane; j < NSYM; j += 32) {
                    int cls = j ? lb[j - 1] : (CC - 1);
                    rrow[j] = exp2f(rp[cls] * LOG2E);
                }
                __syncwarp();
                if (lane == 0) st_rel(&ready[side][slot], t + 1);

                // ---- lse2 of row t (off the ring critical path) ----
                float ssum =
                    exp2f(c0.x*LOG2E)+exp2f(c0.y*LOG2E)+exp2f(c0.z*LOG2E)+exp2f(c0.w*LOG2E)+
                    exp2f(c1.x*LOG2E)+exp2f(c1.y*LOG2E)+exp2f(c1.z*LOG2E)+exp2f(c1.w*LOG2E)+
                    exp2f(c2.x*LOG2E)+exp2f(c2.y*LOG2E)+exp2f(c2.z*LOG2E)+exp2f(c2.w*LOG2E)+
                    exp2f(c3.x*LOG2E)+exp2f(c3.y*LOG2E)+exp2f(c3.z*LOG2E)+exp2f(c3.w*LOG2E);
                #pragma unroll
                for (int o = 16; o; o >>= 1) ssum += __shfl_xor_sync(0xffffffffu, ssum, o);
                if (lane == 0) lse_s[side][t] = log2f(ssum);

                // rotate pipeline
                c0 = d0; c1 = d1; c2 = d2; c3 = d3;
                d0 = e0; d1 = e1; d2 = e2; d3 = e3;
                t += 7;
                rp = bbase + (size_t)t * CC;
            }
        }
        __syncwarp();
        if (lane == 0) st_rel(&pdone[side][pw], 1);
    } else {
        // =================== CONSUMER ===================
        int side = warp - 14;
        int b    = blockIdx.x * 2 + side;
        int s0   = lane * 5;
        const int* lb = labels_s[side];
        float* rs = &ring[side][0][0];
        int*  rdy = &ready[side][0];

        int   idx[5];
        float skipf[5];
        #pragma unroll
        for (int k = 0; k < 5; ++k) {
            int s = s0 + k;
            int ks = s >> 1;
            if ((s & 1) && s < SS) {
                idx[k]   = 1 + ks;
                skipf[k] = (s >= 3 && lb[ks] != lb[ks - 1]) ? 1.f : 0.f;
            } else {
                idx[k]   = 0;
                skipf[k] = 0.f;
            }
        }

        int tend = log_len[b] - 1;
        int send = 2 * lab_len[b];

        while (ld_acq(&rdy[0]) < 1) __nanosleep(60);
        float a[5];
        a[0] = (s0 == 0) ? rs[idx[0]] : 0.f;
        a[1] = (s0 == 0) ? rs[idx[1]] : 0.f;
        a[2] = 0.f; a[3] = 0.f; a[4] = 0.f;
        int   ez = (s0 == 0) ? 0 : EZ_EMPTY;
        float si;

        float cf0 = 0.f, cf1 = 0.f;
        int   cez0 = 0, cez1 = 0;
        if (tend == 0) {
            #pragma unroll
            for (int k = 0; k < 5; ++k) {
                if (s0 + k == send)     { cf0 = a[k]; cez0 = ez; }
                if (s0 + k == send - 1) { cf1 = a[k]; cez1 = ez; }
            }
        }

        #define RENORM_EXCHANGE() do {                                             \
            float w_ = fmaxf(fmaxf(fmaxf(a[0], a[1]), fmaxf(a[2], a[3])), a[4]);   \
            unsigned wu_ = __float_as_uint(w_);                                     \
            int ex_, eznew_;                                                        \
            if (wu_ != 0u) { ex_ = (int)((wu_ >> 23) & 255) - 127; eznew_ = ez + ex_; } \
            else           { ex_ = 0; eznew_ = EZ_EMPTY; }                          \
            int en_ = __shfl_up_sync(0xffffffffu, eznew_, 1);                       \
            if (lane == 0) en_ = EZ_EMPTY;                                          \
            int mz_ = max(eznew_, en_);                                             \
            float cs_ = exp2i_pm(-ex_ + ((eznew_ - mz_ < -127) ? -127 : (eznew_ - mz_))); \
            if (eznew_ == EZ_EMPTY) cs_ = 0.f;                                      \
            a[0] *= cs_; a[1] *= cs_; a[2] *= cs_; a[3] *= cs_; a[4] *= cs_;        \
            ez = (mz_ == EZ_EMPTY) ? EZ_EMPTY : mz_;                                \
            si = (lane == 0) ? 0.f : exp2i_pm((en_ - ez < -127) ? -127 : (en_ - ez)); \
            if (lane == 0) si = 0.f;                                                \
        } while (0)

        #define STEPR(E_, T_) do {                                                  \
            float p4 = __shfl_up_sync(0xffffffffu, a[4], 1) * si;                   \
            float p3 = __shfl_up_sync(0xffffffffu, a[3], 1) * si;                   \
            float n0 = fmaf(skipf[0], p3,   a[0] + p4)   * (E_)[0];                 \
            float n1 = fmaf(skipf[1], p4,   a[1] + a[0]) * (E_)[1];                 \
            float n2 = fmaf(skipf[2], a[0], a[2] + a[1]) * (E_)[2];                 \
            float n3 = fmaf(skipf[3], a[1], a[3] + a[2]) * (E_)[3];                 \
            float n4 = fmaf(skipf[4], a[2], a[4] + a[3]) * (E_)[4];                 \
            a[0] = n0; a[1] = n1; a[2] = n2; a[3] = n3; a[4] = n4;                  \
            if (__builtin_expect((T_) == tend, 0)) {                                \
                if (s0     == send)     { cf0 = a[0]; cez0 = ez; }                  \
                if (s0 + 1 == send)     { cf0 = a[1]; cez0 = ez; }                  \
                if (s0 + 2 == send)     { cf0 = a[2]; cez0 = ez; }                  \
                if (s0 + 3 == send)     { cf0 = a[3]; cez0 = ez; }                  \
                if (s0 + 4 == send)     { cf0 = a[4]; cez0 = ez; }                  \
                if (s0     == send - 1) { cf1 = a[0]; cez1 = ez; }                  \
                if (s0 + 1 == send - 1) { cf1 = a[1]; cez1 = ez; }                  \
                if (s0 + 2 == send - 1) { cf1 = a[2]; cez1 = ez; }                  \
                if (s0 + 3 == send - 1) { cf1 = a[3]; cez1 = ez; }                  \
                if (s0 + 4 == send - 1) { cf1 = a[4]; cez1 = ez; }                  \
            }                                                                       \
        } while (0)

        RENORM_EXCHANGE();   // si for t = 1..4

        for (int g = 0; g < 63; ++g) {
            int t0 = 1 + 4 * g;
            int sA = t0 & 31, sB = (t0 + 1) & 31, sC = (t0 + 2) & 31, sD = (t0 + 3) & 31;
            for (;;) {
                int rA = ld_acq(&rdy[sA]);
                int rB = ld_acq(&rdy[sB]);
                int rC = ld_acq(&rdy[sC]);
                int rD = ld_acq(&rdy[sD]);
                if (rA > t0 && rB > t0 + 1 && rC > t0 + 2 && rD > t0 + 3) break;
                __nanosleep(60);
            }
            const float* pA = rs + sA * RW;
            const float* pB = rs + sB * RW;
            const float* pC = rs + sC * RW;
            const float* pD = rs + sD * RW;
            float eA[5], eB[5], eC[5], eD[5];
            #pragma unroll
            for (int k = 0; k < 5; ++k) {
                eA[k] = pA[idx[k]]; eB[k] = pB[idx[k]];
                eC[k] = pC[idx[k]]; eD[k] = pD[idx[k]];
            }
            STEPR(eA, t0); STEPR(eB, t0 + 1); STEPR(eC, t0 + 2); STEPR(eD, t0 + 3);
            RENORM_EXCHANGE();
            st_rel(&consT[side], t0 + 3);
        }
        #pragma unroll
        for (int t = 253; t <= 255; ++t) {
            int sl = t & 31;
            while (ld_acq(&rdy[sl]) < t + 1) __nanosleep(60);
            const float* p = rs + sl * RW;
            float eT[5];
            #pragma unroll
            for (int k = 0; k < 5; ++k) eT[k] = p[idx[k]];
            STEPR(eT, t);
        }
        st_rel(&consT[side], 255);

        // ---- normalization correction: wait for producers, sum lse2 ----
        if (lane < 7) {
            while (ld_acq(&pdone[side][lane]) == 0) __nanosleep(60);
        }
        __syncwarp();
        float lsesum = 0.f;
        for (int t = lane; t < TT; t += 32)
            if (t <= tend) lsesum += lse_s[side][t];
        #pragma unroll
        for (int o = 16; o; o >>= 1) lsesum += __shfl_xor_sync(0xffffffffu, lsesum, o);

        float v0 = (cf0 > 0.f) ? (logf(cf0) + (float)cez0 * LN2) : -3.0e38f;
        float v1 = (cf1 > 0.f) ? (logf(cf1) + (float)cez1 * LN2) : -3.0e38f;
        #pragma unroll
        for (int o = 16; o; o >>= 1) {
            v0 = fmaxf(v0, __shfl_xor_sync(0xffffffffu, v0, o));
            v1 = fmaxf(v1, __shfl_xor_sync(0xffffffffu, v1, o));
        }
        int is_last = 0;
        if (lane == 0) {
            float mm = fmaxf(v0, v1);
            g_nll[b] = -(mm + logf(expf(v0 - mm) + expf(v1 - mm))) + LN2 * lsesum;
            __threadfence();
            is_last = (atomicAdd(&g_done, 1) == BB - 1);
        }
        is_last = __shfl_sync(0xffffffffu, is_last, 0);
        if (is_last) {
            __threadfence();
            float s_ = 0.f;
            #pragma unroll
            for (int i = 0; i < 8; ++i) s_ += __ldcg(&g_nll[lane * 8 + i]);
            #pragma unroll
            for (int o = 16; o; o >>= 1) s_ += __shfl_xor_sync(0xffffffffu, s_, o);
            if (lane == 0) {
                out[0] = s_ * (1.0f / BB);
                g_done = 0;
                __threadfence();
            }
        }
    }
}

// ---------------------------------------------------------------------------
extern "C" void kernel_launch(void* const* d_in, const int* in_sizes, int n_in,
                              void* d_out, int out_size) {
    const float* logits  = (const float*)d_in[0];
    const int*   labels  = (const int*)  d_in[1];
    const int*   lab_len = (const int*)  d_in[2];
    const int*   log_len = (const int*)  d_in[3];

    k_fused<<<BB / 2, 512>>>(logits, labels, lab_len, log_len, (float*)d_out);
}

// round 14
// speedup vs baseline: 1.1868x; 1.1868x over previous
#include <cuda_runtime.h>

#define BB 256
#define TT 256
#define CC 512
#define LL 64
#define SS 129              // 2L+1 extended states
#define NSYM 65             // [blank, l0..l63]
#define RW 68               // ring row width in floats
#define RING 32             // ring depth (rows)
#define NPROD 11            // producer warps per batch
#define LOG2E 1.4426950408889634f
#define LN2   0.6931471805599453f
#define EZ_EMPTY (-100000)

__device__ float g_nll[BB];
__device__ int   g_done;    // zero-init; reset by winner each launch

__device__ __forceinline__ float exp2i_pm(int d) {
    d = max(d, -127); d = min(d, 127);
    return __uint_as_float((unsigned)(127 + d) << 23);
}
__device__ __forceinline__ int ld_acq(const int* p) {
    int v;
    asm volatile("ld.acquire.cta.shared.b32 %0, [%1];"
                 : "=r"(v) : "r"((unsigned)__cvta_generic_to_shared(p)) : "memory");
    return v;
}
__device__ __forceinline__ void st_rel(int* p, int v) {
    asm volatile("st.release.cta.shared.b32 [%0], %1;"
                 :: "r"((unsigned)__cvta_generic_to_shared(p)), "r"(v) : "memory");
}

// ---------------------------------------------------------------------------
// Fused kernel: 1 block = 1 batch element, 384 threads (12 warps), grid 256.
// 2 blocks co-resident per SM -> ~22 producer warps/SM issuing DRAM loads.
// Warps 0-10: producers (softmax rows -> smem ring, 1-row lookahead).
// Warp 11: consumer (CTC recursion, per-lane pow2 scaling, sleep-backoff).
// ---------------------------------------------------------------------------
__global__ void __launch_bounds__(384, 2) k_fused(const float* __restrict__ logits,
                                                  const int*   __restrict__ labels,
                                                  const int*   __restrict__ lab_len,
                                                  const int*   __restrict__ log_len,
                                                  float* __restrict__ out) {
    __shared__ __align__(16) float ring[RING][RW];
    __shared__ int labels_s[LL];
    __shared__ int ready[RING];   // row t written -> value t+1
    __shared__ int consT;         // consumer progress

    int tid  = threadIdx.x;
    int warp = tid >> 5;
    int lane = tid & 31;
    int b    = blockIdx.x;

    if (tid < LL) labels_s[tid] = labels[b * LL + tid];
    if (tid >= 64 && tid < 64 + RING) ready[tid - 64] = 0;
    if (tid == 96) consT = -1;
    __syncthreads();

    if (warp < NPROD) {
        // =================== PRODUCER ===================
        const int* lb = labels_s;
        int t = warp;
        const float* rp = logits + ((size_t)b * TT + t) * CC;
        const float4* r4 = reinterpret_cast<const float4*>(rp);
        float4 c0 = r4[lane], c1 = r4[lane + 32], c2 = r4[lane + 64], c3 = r4[lane + 96];

        while (t < TT) {
            int tn = t + NPROD;
            const float* rpn = logits + ((size_t)b * TT + (tn < TT ? tn : 0)) * CC;
            const float4* r4n = reinterpret_cast<const float4*>(rpn);
            float4 d0 = r4n[lane], d1 = r4n[lane + 32],
                   d2 = r4n[lane + 64], d3 = r4n[lane + 96];

            float ssum =
                exp2f(c0.x*LOG2E)+exp2f(c0.y*LOG2E)+exp2f(c0.z*LOG2E)+exp2f(c0.w*LOG2E)+
                exp2f(c1.x*LOG2E)+exp2f(c1.y*LOG2E)+exp2f(c1.z*LOG2E)+exp2f(c1.w*LOG2E)+
                exp2f(c2.x*LOG2E)+exp2f(c2.y*LOG2E)+exp2f(c2.z*LOG2E)+exp2f(c2.w*LOG2E)+
                exp2f(c3.x*LOG2E)+exp2f(c3.y*LOG2E)+exp2f(c3.z*LOG2E)+exp2f(c3.w*LOG2E);
            #pragma unroll
            for (int o = 16; o; o >>= 1) ssum += __shfl_xor_sync(0xffffffffu, ssum, o);
            float inv = __fdividef(1.0f, ssum);

            if (t >= RING) {
                while (ld_acq(&consT) < t - (RING - 1)) __nanosleep(50);
            }
            int slot = t & (RING - 1);
            float* rrow = &ring[slot][0];
            #pragma unroll
            for (int j = lane; j < NSYM; j += 32) {
                int cls = j ? lb[j - 1] : (CC - 1);
                rrow[j] = exp2f(rp[cls] * LOG2E) * inv;
            }
            __syncwarp();
            if (lane == 0) st_rel(&ready[slot], t + 1);

            c0 = d0; c1 = d1; c2 = d2; c3 = d3;
            rp = rpn; t = tn;
        }
    } else if (warp == NPROD) {
        // =================== CONSUMER ===================
        int s0 = lane * 5;
        const int* lb = labels_s;
        float* rs = &ring[0][0];
        int*  rdy = &ready[0];

        int   idx[5];
        float skipf[5];
        #pragma unroll
        for (int k = 0; k < 5; ++k) {
            int s = s0 + k;
            int ks = s >> 1;
            if ((s & 1) && s < SS) {
                idx[k]   = 1 + ks;
                skipf[k] = (s >= 3 && lb[ks] != lb[ks - 1]) ? 1.f : 0.f;
            } else {
                idx[k]   = 0;
                skipf[k] = 0.f;
            }
        }

        int tend = log_len[b] - 1;
        int send = 2 * lab_len[b];

        while (ld_acq(&rdy[0]) < 1) __nanosleep(60);
        float a[5];
        a[0] = (s0 == 0) ? rs[idx[0]] : 0.f;
        a[1] = (s0 == 0) ? rs[idx[1]] : 0.f;
        a[2] = 0.f; a[3] = 0.f; a[4] = 0.f;
        int   ez = (s0 == 0) ? 0 : EZ_EMPTY;
        float si;

        float cf0 = 0.f, cf1 = 0.f;
        int   cez0 = 0, cez1 = 0;
        if (tend == 0) {
            #pragma unroll
            for (int k = 0; k < 5; ++k) {
                if (s0 + k == send)     { cf0 = a[k]; cez0 = ez; }
                if (s0 + k == send - 1) { cf1 = a[k]; cez1 = ez; }
            }
        }

        #define RENORM_EXCHANGE() do {                                             \
            float w_ = fmaxf(fmaxf(fmaxf(a[0], a[1]), fmaxf(a[2], a[3])), a[4]);   \
            unsigned wu_ = __float_as_uint(w_);                                     \
            int ex_, eznew_;                                                        \
            if (wu_ != 0u) { ex_ = (int)((wu_ >> 23) & 255) - 127; eznew_ = ez + ex_; } \
            else           { ex_ = 0; eznew_ = EZ_EMPTY; }                          \
            int en_ = __shfl_up_sync(0xffffffffu, eznew_, 1);                       \
            if (lane == 0) en_ = EZ_EMPTY;                                          \
            int mz_ = max(eznew_, en_);                                             \
            float cs_ = exp2i_pm(-ex_ + ((eznew_ - mz_ < -127) ? -127 : (eznew_ - mz_))); \
            if (eznew_ == EZ_EMPTY) cs_ = 0.f;                                      \
            a[0] *= cs_; a[1] *= cs_; a[2] *= cs_; a[3] *= cs_; a[4] *= cs_;        \
            ez = (mz_ == EZ_EMPTY) ? EZ_EMPTY : mz_;                                \
            si = (lane == 0) ? 0.f : exp2i_pm((en_ - ez < -127) ? -127 : (en_ - ez)); \
            if (lane == 0) si = 0.f;                                                \
        } while (0)

        #define STEPR(E_, T_) do {                                                  \
            float p4 = __shfl_up_sync(0xffffffffu, a[4], 1) * si;                   \
            float p3 = __shfl_up_sync(0xffffffffu, a[3], 1) * si;                   \
            float n0 = fmaf(skipf[0], p3,   a[0] + p4)   * (E_)[0];                 \
            float n1 = fmaf(skipf[1], p4,   a[1] + a[0]) * (E_)[1];                 \
            float n2 = fmaf(skipf[2], a[0], a[2] + a[1]) * (E_)[2];                 \
            float n3 = fmaf(skipf[3], a[1], a[3] + a[2]) * (E_)[3];                 \
            float n4 = fmaf(skipf[4], a[2], a[4] + a[3]) * (E_)[4];                 \
            a[0] = n0; a[1] = n1; a[2] = n2; a[3] = n3; a[4] = n4;                  \
            if (__builtin_expect((T_) == tend, 0)) {                                \
                if (s0     == send)     { cf0 = a[0]; cez0 = ez; }                  \
                if (s0 + 1 == send)     { cf0 = a[1]; cez0 = ez; }                  \
                if (s0 + 2 == send)     { cf0 = a[2]; cez0 = ez; }                  \
                if (s0 + 3 == send)     { cf0 = a[3]; cez0 = ez; }                  \
                if (s0 + 4 == send)     { cf0 = a[4]; cez0 = ez; }                  \
                if (s0     == send - 1) { cf1 = a[0]; cez1 = ez; }                  \
                if (s0 + 1 == send - 1) { cf1 = a[1]; cez1 = ez; }                  \
                if (s0 + 2 == send - 1) { cf1 = a[2]; cez1 = ez; }                  \
                if (s0 + 3 == send - 1) { cf1 = a[3]; cez1 = ez; }                  \
                if (s0 + 4 == send - 1) { cf1 = a[4]; cez1 = ez; }                  \
            }                                                                       \
        } while (0)

        RENORM_EXCHANGE();   // si for t = 1..4

        for (int g = 0; g < 63; ++g) {
            int t0 = 1 + 4 * g;
            int sA = t0 & 31, sB = (t0 + 1) & 31, sC = (t0 + 2) & 31, sD = (t0 + 3) & 31;
            for (;;) {
                int rA = ld_acq(&rdy[sA]);
                int rB = ld_acq(&rdy[sB]);
                int rC = ld_acq(&rdy[sC]);
                int rD = ld_acq(&rdy[sD]);
                if (rA > t0 && rB > t0 + 1 && rC > t0 + 2 && rD > t0 + 3) break;
                __nanosleep(60);
            }
            const float* pA = rs + sA * RW;
            const float* pB = rs + sB * RW;
            const float* pC = rs + sC * RW;
            const float* pD = rs + sD * RW;
            float eA[5], eB[5], eC[5], eD[5];
            #pragma unroll
            for (int k = 0; k < 5; ++k) {
                eA[k] = pA[idx[k]]; eB[k] = pB[idx[k]];
                eC[k] = pC[idx[k]]; eD[k] = pD[idx[k]];
            }
            STEPR(eA, t0); STEPR(eB, t0 + 1); STEPR(eC, t0 + 2); STEPR(eD, t0 + 3);
            RENORM_EXCHANGE();
            st_rel(&consT, t0 + 3);
        }
        #pragma unroll
        for (int t = 253; t <= 255; ++t) {
            int sl = t & 31;
            while (ld_acq(&rdy[sl]) < t + 1) __nanosleep(60);
            const float* p = rs + sl * RW;
            float eT[5];
            #pragma unroll
            for (int k = 0; k < 5; ++k) eT[k] = p[idx[k]];
            STEPR(eT, t);
        }
        st_rel(&consT, 255);

        float v0 = (cf0 > 0.f) ? (logf(cf0) + (float)cez0 * LN2) : -3.0e38f;
        float v1 = (cf1 > 0.f) ? (logf(cf1) + (float)cez1 * LN2) : -3.0e38f;
        #pragma unroll
        for (int o = 16; o; o >>= 1) {
            v0 = fmaxf(v0, __shfl_xor_sync(0xffffffffu, v0, o));
            v1 = fmaxf(v1, __shfl_xor_sync(0xffffffffu, v1, o));
        }
        int is_last = 0;
        if (lane == 0) {
            float mm = fmaxf(v0, v1);
            g_nll[b] = -(mm + logf(expf(v0 - mm) + expf(v1 - mm)));
            __threadfence();
            is_last = (atomicAdd(&g_done, 1) == BB - 1);
        }
        is_last = __shfl_sync(0xffffffffu, is_last, 0);
        if (is_last) {
            __threadfence();
            float s_ = 0.f;
            #pragma unroll
            for (int i = 0; i < 8; ++i) s_ += __ldcg(&g_nll[lane * 8 + i]);
            #pragma unroll
            for (int o = 16; o; o >>= 1) s_ += __shfl_xor_sync(0xffffffffu, s_, o);
            if (lane == 0) {
                out[0] = s_ * (1.0f / BB);
                g_done = 0;
                __threadfence();
            }
        }
    }
}

// ---------------------------------------------------------------------------
extern "C" void kernel_launch(void* const* d_in, const int* in_sizes, int n_in,
                              void* d_out, int out_size) {
    const float* logits  = (const float*)d_in[0];
    const int*   labels  = (const int*)  d_in[1];
    const int*   lab_len = (const int*)  d_in[2];
    const int*   log_len = (const int*)  d_in[3];

    k_fused<<<BB, 384>>>(logits, labels, lab_len, log_len, (float*)d_out);
}